// round 5
// baseline (speedup 1.0000x reference)
#include <cuda_runtime.h>
#include <cuda_fp16.h>
#include <cfloat>
#include <cstdint>

#define BB 2048
#define TT 32
#define VV 1024
#define DD 256

// ---------------- static device scratch -------------------------------------
__device__ float g_c2[TT * VV];                                  // 128 KB
// A fragments: [t][mtile(128)][kstep(16)] blocks of 256 half2 (hi 128 | lo 128)
__device__ half2 g_xs[(size_t)TT * 128 * 16 * 256];              // 67 MB
// B fragments: [t][ntile(128)][kstep(16)] blocks of 128 half2 (hi 64 | lo 64)
__device__ half2 g_cs[(size_t)TT * 128 * 16 * 128];              // 33.5 MB

// ---------------- helpers ----------------------------------------------------
__device__ __forceinline__ void mma_f16(float* c, uint32_t a0, uint32_t a1,
                                        uint32_t a2, uint32_t a3,
                                        uint32_t b0, uint32_t b1) {
    asm volatile(
        "mma.sync.aligned.m16n8k16.row.col.f32.f16.f16.f32 "
        "{%0,%1,%2,%3}, {%4,%5,%6,%7}, {%8,%9}, {%0,%1,%2,%3};"
        : "+f"(c[0]), "+f"(c[1]), "+f"(c[2]), "+f"(c[3])
        : "r"(a0), "r"(a1), "r"(a2), "r"(a3), "r"(b0), "r"(b1));
}

// ---------------- kernel 1: c2[t][v] -----------------------------------------
__global__ __launch_bounds__(256) void c2_kernel(const float* __restrict__ cb) {
    int row  = blockIdx.x * 8 + (threadIdx.x >> 5);
    int lane = threadIdx.x & 31;
    const float4* p = reinterpret_cast<const float4*>(cb) + (size_t)row * (DD / 4);
    float s = 0.f;
#pragma unroll
    for (int q = 0; q < 2; q++) {
        float4 v = p[lane + 32 * q];
        s = fmaf(v.x, v.x, s); s = fmaf(v.y, v.y, s);
        s = fmaf(v.z, v.z, s); s = fmaf(v.w, v.w, s);
    }
#pragma unroll
    for (int o = 16; o > 0; o >>= 1) s += __shfl_down_sync(0xffffffffu, s, o);
    if (lane == 0) g_c2[row] = s;
}

// ---------------- kernel 2: split X into A-fragment layout -------------------
// Grid (128 mtiles, 32 t), 128 threads. One block: 16 b-rows x 256 k.
__global__ __launch_bounds__(128) void conv_x_kernel(const float* __restrict__ x) {
    __shared__ float xs[16][258];
    const int mt = blockIdx.x, t = blockIdx.y, tid = threadIdx.x;
    // load 16 rows x 256 floats, coalesced
#pragma unroll
    for (int j = 0; j < 8; j++) {
        int f = tid + j * 128;          // 0..1023 float4s
        int r = f >> 6, d4 = f & 63;
        float4 v = *reinterpret_cast<const float4*>(
            x + ((size_t)(mt * 16 + r) * TT + t) * DD + d4 * 4);
        xs[r][d4 * 4 + 0] = v.x; xs[r][d4 * 4 + 1] = v.y;
        xs[r][d4 * 4 + 2] = v.z; xs[r][d4 * 4 + 3] = v.w;
    }
    __syncthreads();
    const int lane = tid >> 2, r = tid & 3;
    const int grp = lane >> 2, tig = lane & 3;
    const int row = grp + (r & 1) * 8;
    half2* obase = g_xs + ((size_t)(t * 128 + mt) * 16) * 256;
#pragma unroll
    for (int ks = 0; ks < 16; ks++) {
        int k = ks * 16 + (r >> 1) * 8 + tig * 2;
        float v0 = xs[row][k], v1 = xs[row][k + 1];
        half h0 = __float2half_rn(v0), h1 = __float2half_rn(v1);
        half l0 = __float2half_rn(v0 - __half2float(h0));
        half l1 = __float2half_rn(v1 - __half2float(h1));
        obase[ks * 256 + tid]       = __halves2half2(h0, h1);
        obase[ks * 256 + 128 + tid] = __halves2half2(l0, l1);
    }
}

// ---------------- kernel 3: split C into B-fragment layout -------------------
// Grid (64 vtile16, 32 t), 128 threads. One block: 16 v-rows x 256 k.
__global__ __launch_bounds__(128) void conv_c_kernel(const float* __restrict__ cb) {
    __shared__ float cs[16][258];
    const int vt = blockIdx.x, t = blockIdx.y, tid = threadIdx.x;
#pragma unroll
    for (int j = 0; j < 8; j++) {
        int f = tid + j * 128;
        int r = f >> 6, d4 = f & 63;
        float4 v = *reinterpret_cast<const float4*>(
            cb + ((size_t)t * VV + vt * 16 + r) * DD + d4 * 4);
        cs[r][d4 * 4 + 0] = v.x; cs[r][d4 * 4 + 1] = v.y;
        cs[r][d4 * 4 + 2] = v.z; cs[r][d4 * 4 + 3] = v.w;
    }
    __syncthreads();
    // u = tid: s = u>>6 (which 8-row ntile), w = u&63: lane = w>>1, rr = w&1
    const int s = tid >> 6, w = tid & 63;
    const int lane = w >> 1, rr = w & 1;
    const int grp = lane >> 2, tig = lane & 3;
    const int row = s * 8 + grp;
#pragma unroll
    for (int ks = 0; ks < 16; ks++) {
        int k = ks * 16 + rr * 8 + tig * 2;
        float v0 = cs[row][k], v1 = cs[row][k + 1];
        half h0 = __float2half_rn(v0), h1 = __float2half_rn(v1);
        half l0 = __float2half_rn(v0 - __half2float(h0));
        half l1 = __float2half_rn(v1 - __half2float(h1));
        half2* ob = g_cs + ((size_t)(t * 128 + vt * 2 + s) * 16 + ks) * 128;
        ob[w]      = __halves2half2(h0, h1);
        ob[64 + w] = __halves2half2(l0, l1);
    }
}

// ---------------- main kernel ------------------------------------------------
// Grid (16, 32), 128 threads = 4 warps (2m x 2n). Warp tile 64x64; block 128x128.
// No smem operands: fragments LDG'd directly from L2-resident split scratch.
__global__ __launch_bounds__(128, 2)
void vsq_mma_kernel(const float* __restrict__ cb, float* __restrict__ out) {
    __shared__ float c2s[VV];
    __shared__ float Sv[128][8];
    __shared__ int   Si[128][8];
    __shared__ int   ridx[128];

    const int tid = threadIdx.x;
    const int btile = blockIdx.x, t = blockIdx.y;
    const int wid = tid >> 5, lane = tid & 31;
    const int grp = lane >> 2, tig = lane & 3;
    const int wm = wid >> 1, wn = wid & 1;

    for (int i = tid; i < VV; i += 128) c2s[i] = g_c2[t * VV + i];
    __syncthreads();

    float bestv[8];
    int   besti[8];
#pragma unroll
    for (int i = 0; i < 8; i++) { bestv[i] = FLT_MAX; besti[i] = 0; }

    // A fragment base for this warp's 4 m-tiles (advance by ks*256 inside)
    const half2* Ab = g_xs + ((size_t)(t * 128 + btile * 8 + wm * 4) * 16) * 256;

    for (int nch = 0; nch < 8; nch++) {
        const half2* Bb = g_cs + ((size_t)(t * 128 + nch * 16 + wn * 8) * 16) * 128;

        float acc[4][8][4];
#pragma unroll
        for (int a = 0; a < 4; a++)
#pragma unroll
            for (int b = 0; b < 8; b++)
#pragma unroll
                for (int c = 0; c < 4; c++) acc[a][b][c] = 0.f;

#pragma unroll 1
        for (int ks = 0; ks < 16; ks++) {
            uint4 AH[4], AL[4];
            uint2 BH[8], BL[8];
#pragma unroll
            for (int mt = 0; mt < 4; mt++) {
                const half2* ab = Ab + ((size_t)mt * 16 + ks) * 256;
                AH[mt] = *reinterpret_cast<const uint4*>(ab + lane * 4);
                AL[mt] = *reinterpret_cast<const uint4*>(ab + 128 + lane * 4);
            }
#pragma unroll
            for (int q = 0; q < 8; q++) {
                const half2* bb = Bb + ((size_t)q * 16 + ks) * 128;
                BH[q] = *reinterpret_cast<const uint2*>(bb + lane * 2);
                BL[q] = *reinterpret_cast<const uint2*>(bb + 64 + lane * 2);
            }
#pragma unroll
            for (int q = 0; q < 8; q++) {
#pragma unroll
                for (int mt = 0; mt < 4; mt++) {
                    mma_f16(acc[mt][q], AH[mt].x, AH[mt].y, AH[mt].z, AH[mt].w, BH[q].x, BH[q].y);
                    mma_f16(acc[mt][q], AH[mt].x, AH[mt].y, AH[mt].z, AH[mt].w, BL[q].x, BL[q].y);
                    mma_f16(acc[mt][q], AL[mt].x, AL[mt].y, AL[mt].z, AL[mt].w, BH[q].x, BH[q].y);
                }
            }
        }
        // fold c2, running argmin (v ascending within thread)
#pragma unroll
        for (int q = 0; q < 8; q++) {
            int vbase = nch * 128 + wn * 64 + q * 8 + tig * 2;
            float c0 = c2s[vbase], c1 = c2s[vbase + 1];
#pragma unroll
            for (int mt = 0; mt < 4; mt++) {
                float s0 = fmaf(-2.f, acc[mt][q][0], c0);
                float s1 = fmaf(-2.f, acc[mt][q][1], c1);
                float s2 = fmaf(-2.f, acc[mt][q][2], c0);
                float s3 = fmaf(-2.f, acc[mt][q][3], c1);
                int sl0 = mt * 2, sl1 = mt * 2 + 1;
                if (s0 < bestv[sl0]) { bestv[sl0] = s0; besti[sl0] = vbase; }
                if (s1 < bestv[sl0]) { bestv[sl0] = s1; besti[sl0] = vbase + 1; }
                if (s2 < bestv[sl1]) { bestv[sl1] = s2; besti[sl1] = vbase; }
                if (s3 < bestv[sl1]) { bestv[sl1] = s3; besti[sl1] = vbase + 1; }
            }
        }
    }

    // cross-thread reduce: 8 candidates per row
#pragma unroll
    for (int mt = 0; mt < 4; mt++) {
#pragma unroll
        for (int h = 0; h < 2; h++) {
            int r = wm * 64 + mt * 16 + grp + h * 8;
            Sv[r][wn * 4 + tig] = bestv[mt * 2 + h];
            Si[r][wn * 4 + tig] = besti[mt * 2 + h];
        }
    }
    __syncthreads();
    {
        float bv = Sv[tid][0];
        int   bi = Si[tid][0];
#pragma unroll
        for (int u = 1; u < 8; u++) {
            float v2 = Sv[tid][u];
            int   i2 = Si[tid][u];
            if (v2 < bv || (v2 == bv && i2 < bi)) { bv = v2; bi = i2; }
        }
        ridx[tid] = bi;
        int b = btile * 128 + tid;
        out[(size_t)BB * TT * DD + (size_t)b * TT + t] = (float)bi;
    }
    __syncthreads();

    // gather epilogue: embed[b,t,:] = codebook[t, idx, :]
    const float4* cb4  = reinterpret_cast<const float4*>(cb);
    float4*       out4 = reinterpret_cast<float4*>(out);
    int rsub = tid >> 6, d4 = tid & 63;
#pragma unroll 4
    for (int r0 = 0; r0 < 128; r0 += 2) {
        int r   = r0 + rsub;
        int b   = btile * 128 + r;
        int idx = ridx[r];
        out4[((size_t)b * TT + t) * (DD / 4) + d4] =
            cb4[((size_t)t * VV + idx) * (DD / 4) + d4];
    }
}

// ---------------------------------------------------------------------------
extern "C" void kernel_launch(void* const* d_in, const int* in_sizes, int n_in,
                              void* d_out, int out_size) {
    const float* x  = (const float*)d_in[0];   // (B, T, D) f32
    const float* cb = (const float*)d_in[1];   // (T, V, D) f32
    float* out = (float*)d_out;

    c2_kernel<<<(TT * VV) / 8, 256>>>(cb);
    conv_x_kernel<<<dim3(128, TT), 128>>>(x);
    conv_c_kernel<<<dim3(64, TT), 128>>>(cb);
    vsq_mma_kernel<<<dim3(BB / 128, TT), 128>>>(cb, out);
}

// round 6
// speedup vs baseline: 1.2464x; 1.2464x over previous
#include <cuda_runtime.h>
#include <cuda_fp16.h>
#include <cfloat>
#include <cstdint>

#define BB 2048
#define TT 32
#define VV 1024
#define DD 256

// ---------------- static device scratch -------------------------------------
__device__ float g_c2[TT * VV];                                  // 128 KB
// A fragments: [t][mtile16(128)][kstep(16)] blocks of 256 half2 (hi 128 | lo 128)
__device__ half2 g_xs[(size_t)TT * 128 * 16 * 256];              // 67 MB
// B fragments: [t][ntile8(128)][kstep(16)] blocks of 128 half2 (hi 64 | lo 64)
__device__ half2 g_cs[(size_t)TT * 128 * 16 * 128];              // 33.5 MB

// ---------------- helpers ----------------------------------------------------
__device__ __forceinline__ void mma_f16(float* c, uint32_t a0, uint32_t a1,
                                        uint32_t a2, uint32_t a3,
                                        uint32_t b0, uint32_t b1) {
    asm volatile(
        "mma.sync.aligned.m16n8k16.row.col.f32.f16.f16.f32 "
        "{%0,%1,%2,%3}, {%4,%5,%6,%7}, {%8,%9}, {%0,%1,%2,%3};"
        : "+f"(c[0]), "+f"(c[1]), "+f"(c[2]), "+f"(c[3])
        : "r"(a0), "r"(a1), "r"(a2), "r"(a3), "r"(b0), "r"(b1));
}
__device__ __forceinline__ uint32_t smem_u32(const void* p) {
    uint32_t a;
    asm("{ .reg .u64 t; cvta.to.shared.u64 t, %1; cvt.u32.u64 %0, t; }" : "=r"(a) : "l"(p));
    return a;
}
__device__ __forceinline__ void cp16(uint32_t dst, const void* src) {
    asm volatile("cp.async.cg.shared.global [%0], [%1], 16;" :: "r"(dst), "l"(src));
}
#define CP_COMMIT() asm volatile("cp.async.commit_group;")
#define CP_WAIT(n)  asm volatile("cp.async.wait_group %0;" :: "n"(n))

// ---------------- kernel 1: c2[t][v] -----------------------------------------
__global__ __launch_bounds__(256) void c2_kernel(const float* __restrict__ cb) {
    int row  = blockIdx.x * 8 + (threadIdx.x >> 5);
    int lane = threadIdx.x & 31;
    const float4* p = reinterpret_cast<const float4*>(cb) + (size_t)row * (DD / 4);
    float s = 0.f;
#pragma unroll
    for (int q = 0; q < 2; q++) {
        float4 v = p[lane + 32 * q];
        s = fmaf(v.x, v.x, s); s = fmaf(v.y, v.y, s);
        s = fmaf(v.z, v.z, s); s = fmaf(v.w, v.w, s);
    }
#pragma unroll
    for (int o = 16; o > 0; o >>= 1) s += __shfl_down_sync(0xffffffffu, s, o);
    if (lane == 0) g_c2[row] = s;
}

// ---------------- kernel 2: split X into A-fragment layout -------------------
__global__ __launch_bounds__(128) void conv_x_kernel(const float* __restrict__ x) {
    __shared__ float xs[16][258];
    const int mt = blockIdx.x, t = blockIdx.y, tid = threadIdx.x;
#pragma unroll
    for (int j = 0; j < 8; j++) {
        int f = tid + j * 128;
        int r = f >> 6, d4 = f & 63;
        float4 v = *reinterpret_cast<const float4*>(
            x + ((size_t)(mt * 16 + r) * TT + t) * DD + d4 * 4);
        xs[r][d4 * 4 + 0] = v.x; xs[r][d4 * 4 + 1] = v.y;
        xs[r][d4 * 4 + 2] = v.z; xs[r][d4 * 4 + 3] = v.w;
    }
    __syncthreads();
    const int lane = tid >> 2, r = tid & 3;
    const int grp = lane >> 2, tig = lane & 3;
    const int row = grp + (r & 1) * 8;
    half2* obase = g_xs + ((size_t)(t * 128 + mt) * 16) * 256;
#pragma unroll
    for (int ks = 0; ks < 16; ks++) {
        int k = ks * 16 + (r >> 1) * 8 + tig * 2;
        float v0 = xs[row][k], v1 = xs[row][k + 1];
        half h0 = __float2half_rn(v0), h1 = __float2half_rn(v1);
        half l0 = __float2half_rn(v0 - __half2float(h0));
        half l1 = __float2half_rn(v1 - __half2float(h1));
        obase[ks * 256 + tid]       = __halves2half2(h0, h1);
        obase[ks * 256 + 128 + tid] = __halves2half2(l0, l1);
    }
}

// ---------------- kernel 3: split C into B-fragment layout -------------------
__global__ __launch_bounds__(128) void conv_c_kernel(const float* __restrict__ cb) {
    __shared__ float cs[16][258];
    const int vt = blockIdx.x, t = blockIdx.y, tid = threadIdx.x;
#pragma unroll
    for (int j = 0; j < 8; j++) {
        int f = tid + j * 128;
        int r = f >> 6, d4 = f & 63;
        float4 v = *reinterpret_cast<const float4*>(
            cb + ((size_t)t * VV + vt * 16 + r) * DD + d4 * 4);
        cs[r][d4 * 4 + 0] = v.x; cs[r][d4 * 4 + 1] = v.y;
        cs[r][d4 * 4 + 2] = v.z; cs[r][d4 * 4 + 3] = v.w;
    }
    __syncthreads();
    const int s = tid >> 6, w = tid & 63;
    const int lane = w >> 1, rr = w & 1;
    const int grp = lane >> 2, tig = lane & 3;
    const int row = s * 8 + grp;
#pragma unroll
    for (int ks = 0; ks < 16; ks++) {
        int k = ks * 16 + rr * 8 + tig * 2;
        float v0 = cs[row][k], v1 = cs[row][k + 1];
        half h0 = __float2half_rn(v0), h1 = __float2half_rn(v1);
        half l0 = __float2half_rn(v0 - __half2float(h0));
        half l1 = __float2half_rn(v1 - __half2float(h1));
        half2* ob = g_cs + ((size_t)(t * 128 + vt * 2 + s) * 16 + ks) * 128;
        ob[w]      = __halves2half2(h0, h1);
        ob[64 + w] = __halves2half2(l0, l1);
    }
}

// ---------------- main kernel ------------------------------------------------
// Grid (16, 32), 256 threads = 8 warps (2m x 4n). Warp tile 64x32, block 128x128.
// Triple-buffered cp.async of prepacked fragments; LDS.128 fragment loads.
#define SLAB_H2 4096                        // 16 KB per slab (A 8KB + B 8KB)
#define BUF_OFF(b) ((b) * SLAB_H2)
#define NSLAB 128                           // 8 nch x 16 ks

__global__ __launch_bounds__(256, 2)
void vsq_mma_kernel(const float* __restrict__ cb, float* __restrict__ out) {
    extern __shared__ char dyn[];
    half2* sbuf = reinterpret_cast<half2*>(dyn);            // 3 x 16KB
    float* c2s  = reinterpret_cast<float*>(dyn + 49152);    // 4KB
    // reduce arrays alias the pipeline buffers (used only after mainloop)
    float* Sv   = reinterpret_cast<float*>(dyn);            // [128][16]
    int*   Si   = reinterpret_cast<int*>(dyn + 8192);       // [128][16]
    int*   ridx = reinterpret_cast<int*>(dyn + 16384);      // [128]

    const int tid = threadIdx.x;
    const int btile = blockIdx.x, t = blockIdx.y;
    const int wid = tid >> 5, lane = tid & 31;
    const int grp = lane >> 2, tig = lane & 3;
    const int wm = wid >> 2, wn = wid & 3;

    for (int i = tid; i < VV; i += 256) c2s[i] = g_c2[t * VV + i];
    __syncthreads();

    float bestv[8];
    int   besti[8];
#pragma unroll
    for (int i = 0; i < 8; i++) { bestv[i] = FLT_MAX; besti[i] = 0; }

    const half2* Abase = g_xs + ((size_t)(t * 128 + btile * 8) * 16) * 256;
    const half2* Bbase = g_cs + ((size_t)(t * 128)) * 16 * 128;

    // staging: warp wid copies A mtile=wid (1KB) + B ntile8 pair (2x512B)
    const uint32_t sb0 = smem_u32(sbuf);
    auto stage = [&](int s, int buf) {
        int nch = s >> 4, ks = s & 15;
        uint32_t d = sb0 + BUF_OFF(buf) * 4;
        // A: mtile = wid, 256 half2 block; thread copies 32B at lane*8
        const half2* asrc = Abase + ((size_t)(wid * 16 + ks)) * 256 + lane * 8;
        cp16(d + (wid * 256 + lane * 8) * 4, asrc);
        cp16(d + (wid * 256 + lane * 8 + 4) * 4, asrc + 4);
        // B: ntile8 = wid*2 + (lane>>4), 128 half2 block; 32B at (lane&15)*8
        int nt8 = wid * 2 + (lane >> 4);
        int off = (lane & 15) * 8;
        const half2* bsrc = Bbase + ((size_t)((nch * 16 + nt8) * 16 + ks)) * 128 + off;
        uint32_t bd = d + (2048 + nt8 * 128 + off) * 4;
        cp16(bd, bsrc);
        cp16(bd + 16, bsrc + 4);
        CP_COMMIT();
    };

    stage(0, 0);
    stage(1, 1);

    float acc[4][4][4];
#pragma unroll
    for (int a = 0; a < 4; a++)
#pragma unroll
        for (int b = 0; b < 4; b++)
#pragma unroll
            for (int c = 0; c < 4; c++) acc[a][b][c] = 0.f;

    for (int s = 0; s < NSLAB; s++) {
        if (s < NSLAB - 2) { CP_WAIT(1); } else { CP_WAIT(0); }
        __syncthreads();
        const int buf = s % 3;
        half2* Asm = sbuf + BUF_OFF(buf);
        half2* Bsm = Asm + 2048;

        uint4 AH[4], AL[4];
        uint2 BH[4], BL[4];
#pragma unroll
        for (int mt = 0; mt < 4; mt++) {
            half2* ab = Asm + (wm * 4 + mt) * 256;
            AH[mt] = *reinterpret_cast<uint4*>(ab + lane * 4);
            AL[mt] = *reinterpret_cast<uint4*>(ab + 128 + lane * 4);
        }
#pragma unroll
        for (int q = 0; q < 4; q++) {
            half2* bb = Bsm + (wn * 4 + q) * 128;
            BH[q] = *reinterpret_cast<uint2*>(bb + lane * 2);
            BL[q] = *reinterpret_cast<uint2*>(bb + 64 + lane * 2);
        }
#pragma unroll
        for (int q = 0; q < 4; q++)
#pragma unroll
            for (int mt = 0; mt < 4; mt++) {
                mma_f16(acc[mt][q], AH[mt].x, AH[mt].y, AH[mt].z, AH[mt].w, BH[q].x, BH[q].y);
                mma_f16(acc[mt][q], AH[mt].x, AH[mt].y, AH[mt].z, AH[mt].w, BL[q].x, BL[q].y);
                mma_f16(acc[mt][q], AL[mt].x, AL[mt].y, AL[mt].z, AL[mt].w, BH[q].x, BH[q].y);
            }
        __syncthreads();
        if (s + 2 < NSLAB) stage(s + 2, (s + 2) % 3);

        if ((s & 15) == 15) {
            // end of K for this nch: fold c2, update argmin, reset acc
            const int nch = s >> 4;
#pragma unroll
            for (int q = 0; q < 4; q++) {
                int vbase = nch * 128 + (wn * 4 + q) * 8 + tig * 2;
                float c0 = c2s[vbase], c1 = c2s[vbase + 1];
#pragma unroll
                for (int mt = 0; mt < 4; mt++) {
                    float s0 = fmaf(-2.f, acc[mt][q][0], c0);
                    float s1 = fmaf(-2.f, acc[mt][q][1], c1);
                    float s2 = fmaf(-2.f, acc[mt][q][2], c0);
                    float s3 = fmaf(-2.f, acc[mt][q][3], c1);
                    int sl0 = mt * 2, sl1 = mt * 2 + 1;
                    if (s0 < bestv[sl0]) { bestv[sl0] = s0; besti[sl0] = vbase; }
                    if (s1 < bestv[sl0]) { bestv[sl0] = s1; besti[sl0] = vbase + 1; }
                    if (s2 < bestv[sl1]) { bestv[sl1] = s2; besti[sl1] = vbase; }
                    if (s3 < bestv[sl1]) { bestv[sl1] = s3; besti[sl1] = vbase + 1; }
                    acc[mt][q][0] = 0.f; acc[mt][q][1] = 0.f;
                    acc[mt][q][2] = 0.f; acc[mt][q][3] = 0.f;
                }
            }
        }
    }

    // cross-thread reduce: 16 candidates per row (aliases pipeline smem)
    __syncthreads();
#pragma unroll
    for (int mt = 0; mt < 4; mt++) {
#pragma unroll
        for (int h = 0; h < 2; h++) {
            int r = wm * 64 + mt * 16 + grp + h * 8;
            Sv[r * 16 + wn * 4 + tig] = bestv[mt * 2 + h];
            Si[r * 16 + wn * 4 + tig] = besti[mt * 2 + h];
        }
    }
    __syncthreads();
    if (tid < 128) {
        float bv = Sv[tid * 16];
        int   bi = Si[tid * 16];
#pragma unroll
        for (int u = 1; u < 16; u++) {
            float v2 = Sv[tid * 16 + u];
            int   i2 = Si[tid * 16 + u];
            if (v2 < bv || (v2 == bv && i2 < bi)) { bv = v2; bi = i2; }
        }
        ridx[tid] = bi;
        int b = btile * 128 + tid;
        out[(size_t)BB * TT * DD + (size_t)b * TT + t] = (float)bi;
    }
    __syncthreads();

    // gather epilogue
    const float4* cb4  = reinterpret_cast<const float4*>(cb);
    float4*       out4 = reinterpret_cast<float4*>(out);
    int rsub = tid >> 6, d4 = tid & 63;
#pragma unroll 4
    for (int r0 = 0; r0 < 128; r0 += 4) {
        int r   = r0 + rsub;
        int b   = btile * 128 + r;
        int idx = ridx[r];
        out4[((size_t)b * TT + t) * (DD / 4) + d4] =
            cb4[((size_t)t * VV + idx) * (DD / 4) + d4];
    }
}

// ---------------------------------------------------------------------------
#define DYN_SMEM (49152 + VV * 4)

extern "C" void kernel_launch(void* const* d_in, const int* in_sizes, int n_in,
                              void* d_out, int out_size) {
    const float* x  = (const float*)d_in[0];   // (B, T, D) f32
    const float* cb = (const float*)d_in[1];   // (T, V, D) f32
    float* out = (float*)d_out;

    cudaFuncSetAttribute(vsq_mma_kernel, cudaFuncAttributeMaxDynamicSharedMemorySize, DYN_SMEM);
    c2_kernel<<<(TT * VV) / 8, 256>>>(cb);
    conv_x_kernel<<<dim3(128, TT), 128>>>(x);
    conv_c_kernel<<<dim3(64, TT), 128>>>(cb);
    vsq_mma_kernel<<<dim3(BB / 128, TT), 256, DYN_SMEM>>>(cb, out);
}

// round 7
// speedup vs baseline: 1.3305x; 1.0675x over previous
#include <cuda_runtime.h>
#include <cuda_fp16.h>
#include <cfloat>
#include <cstdint>

#define BB 2048
#define TT 32
#define VV 1024
#define DD 256

// ---------------- static device scratch -------------------------------------
__device__ float g_c2[TT * VV];                                  // 128 KB
// A fragments: [t][mtile16(128)][kstep(16)] blocks of 256 half2 (hi 128 | lo 128)
__device__ half2 g_xs[(size_t)TT * 128 * 16 * 256];              // 67 MB
// B fragments: [t][ntile8(128)][kstep(16)] blocks of 128 half2 (hi 64 | lo 64)
__device__ half2 g_cs[(size_t)TT * 128 * 16 * 128];              // 33.5 MB

// ---------------- helpers ----------------------------------------------------
__device__ __forceinline__ void mma_f16(float* c, uint32_t a0, uint32_t a1,
                                        uint32_t a2, uint32_t a3,
                                        uint32_t b0, uint32_t b1) {
    asm volatile(
        "mma.sync.aligned.m16n8k16.row.col.f32.f16.f16.f32 "
        "{%0,%1,%2,%3}, {%4,%5,%6,%7}, {%8,%9}, {%0,%1,%2,%3};"
        : "+f"(c[0]), "+f"(c[1]), "+f"(c[2]), "+f"(c[3])
        : "r"(a0), "r"(a1), "r"(a2), "r"(a3), "r"(b0), "r"(b1));
}
__device__ __forceinline__ uint32_t smem_u32(const void* p) {
    uint32_t a;
    asm("{ .reg .u64 t; cvta.to.shared.u64 t, %1; cvt.u32.u64 %0, t; }" : "=r"(a) : "l"(p));
    return a;
}
__device__ __forceinline__ void cp16(uint32_t dst, const void* src) {
    asm volatile("cp.async.cg.shared.global [%0], [%1], 16;" :: "r"(dst), "l"(src));
}
#define CP_COMMIT() asm volatile("cp.async.commit_group;")
#define CP_WAIT(n)  asm volatile("cp.async.wait_group %0;" :: "n"(n))

// ---------------- kernel 1: split X into A-fragment layout -------------------
__global__ __launch_bounds__(128) void conv_x_kernel(const float* __restrict__ x) {
    __shared__ float xs[16][258];
    const int mt = blockIdx.x, t = blockIdx.y, tid = threadIdx.x;
#pragma unroll
    for (int j = 0; j < 8; j++) {
        int f = tid + j * 128;
        int r = f >> 6, d4 = f & 63;
        float4 v = *reinterpret_cast<const float4*>(
            x + ((size_t)(mt * 16 + r) * TT + t) * DD + d4 * 4);
        xs[r][d4 * 4 + 0] = v.x; xs[r][d4 * 4 + 1] = v.y;
        xs[r][d4 * 4 + 2] = v.z; xs[r][d4 * 4 + 3] = v.w;
    }
    __syncthreads();
    const int lane = tid >> 2, r = tid & 3;
    const int tig = lane & 3;
    const int grp = lane >> 2;
    const int row = grp + (r & 1) * 8;
    half2* obase = g_xs + ((size_t)(t * 128 + mt) * 16) * 256;
#pragma unroll
    for (int ks = 0; ks < 16; ks++) {
        int k = ks * 16 + (r >> 1) * 8 + tig * 2;
        float v0 = xs[row][k], v1 = xs[row][k + 1];
        half h0 = __float2half_rn(v0), h1 = __float2half_rn(v1);
        half l0 = __float2half_rn(v0 - __half2float(h0));
        half l1 = __float2half_rn(v1 - __half2float(h1));
        obase[ks * 256 + tid]       = __halves2half2(h0, h1);
        obase[ks * 256 + 128 + tid] = __halves2half2(l0, l1);
    }
}

// ---------------- kernel 2: split C into B-fragment layout + c2 --------------
__global__ __launch_bounds__(128) void conv_c_kernel(const float* __restrict__ cb) {
    __shared__ float cs[16][258];
    __shared__ float psum[16][8];
    const int vt = blockIdx.x, t = blockIdx.y, tid = threadIdx.x;
#pragma unroll
    for (int j = 0; j < 8; j++) {
        int f = tid + j * 128;
        int r = f >> 6, d4 = f & 63;
        float4 v = *reinterpret_cast<const float4*>(
            cb + ((size_t)t * VV + vt * 16 + r) * DD + d4 * 4);
        cs[r][d4 * 4 + 0] = v.x; cs[r][d4 * 4 + 1] = v.y;
        cs[r][d4 * 4 + 2] = v.z; cs[r][d4 * 4 + 3] = v.w;
    }
    __syncthreads();
    // c2 partials: thread covers row=tid>>3, k-seg (tid&7)*32..+32
    {
        int r = tid >> 3, seg = tid & 7;
        float s = 0.f;
#pragma unroll
        for (int k = 0; k < 32; k++) {
            float v = cs[r][seg * 32 + k];
            s = fmaf(v, v, s);
        }
        psum[r][seg] = s;
    }
    const int s = tid >> 6, w = tid & 63;
    const int lane = w >> 1, rr = w & 1;
    const int grp = lane >> 2, tig = lane & 3;
    const int row = s * 8 + grp;
#pragma unroll
    for (int ks = 0; ks < 16; ks++) {
        int k = ks * 16 + rr * 8 + tig * 2;
        float v0 = cs[row][k], v1 = cs[row][k + 1];
        half h0 = __float2half_rn(v0), h1 = __float2half_rn(v1);
        half l0 = __float2half_rn(v0 - __half2float(h0));
        half l1 = __float2half_rn(v1 - __half2float(h1));
        half2* ob = g_cs + ((size_t)(t * 128 + vt * 2 + s) * 16 + ks) * 128;
        ob[w]      = __halves2half2(h0, h1);
        ob[64 + w] = __halves2half2(l0, l1);
    }
    __syncthreads();
    if (tid < 16) {
        float acc = 0.f;
#pragma unroll
        for (int j = 0; j < 8; j++) acc += psum[tid][j];
        g_c2[t * VV + vt * 16 + tid] = acc;
    }
}

// ---------------- main kernel ------------------------------------------------
// Grid (16, 32), 256 threads = 8 warps (2m x 4n). Warp tile 64x32, block 128x128.
// Stages of 2 k-steps (32KB), triple-buffered cp.async, ONE barrier per stage.
#define STAGE_H2 8192                       // 32 KB per stage (A 16KB + B 16KB)
#define NSTAGE 64                           // 8 nch x 8 kspair

__global__ __launch_bounds__(256, 2)
void vsq_mma_kernel(const float* __restrict__ cb, float* __restrict__ out) {
    extern __shared__ char dyn[];
    half2* sbuf = reinterpret_cast<half2*>(dyn);            // 3 x 32KB
    float* c2s  = reinterpret_cast<float*>(dyn + 98304);    // 4KB
    // reduce arrays alias pipeline buffers (used only after mainloop)
    float* Sv   = reinterpret_cast<float*>(dyn);            // [128][16]
    int*   Si   = reinterpret_cast<int*>(dyn + 8192);       // [128][16]
    int*   ridx = reinterpret_cast<int*>(dyn + 16384);      // [128]

    const int tid = threadIdx.x;
    const int btile = blockIdx.x, t = blockIdx.y;
    const int wid = tid >> 5, lane = tid & 31;
    const int grp = lane >> 2, tig = lane & 3;
    const int wm = wid >> 2, wn = wid & 3;

    for (int i = tid; i < VV; i += 256) c2s[i] = g_c2[t * VV + i];
    __syncthreads();

    float bestv[8];
    int   besti[8];
#pragma unroll
    for (int i = 0; i < 8; i++) { bestv[i] = FLT_MAX; besti[i] = 0; }

    const half2* Abase = g_xs + ((size_t)(t * 128 + btile * 8) * 16) * 256;
    const half2* Bbase = g_cs + ((size_t)(t * 128)) * 16 * 128;

    const uint32_t sb0 = smem_u32(sbuf);
    const int nt8 = wid * 2 + (lane >> 4);
    const int boff = (lane & 15) * 8;
    // stage st covers nch = st>>3, ks = (st&7)*2 and +1
    auto stage = [&](int st, int buf) {
        const int nch = st >> 3, ks0 = (st & 7) * 2;
        uint32_t d = sb0 + (uint32_t)buf * STAGE_H2 * 4;
#pragma unroll
        for (int sub = 0; sub < 2; sub++) {
            int ks = ks0 + sub;
            const half2* asrc = Abase + ((size_t)(wid * 16 + ks)) * 256 + lane * 8;
            uint32_t ad = d + (sub * 2048 + wid * 256 + lane * 8) * 4;
            cp16(ad, asrc);
            cp16(ad + 16, asrc + 4);
            const half2* bsrc = Bbase + ((size_t)((nch * 16 + nt8) * 16 + ks)) * 128 + boff;
            uint32_t bd = d + (4096 + sub * 2048 + nt8 * 128 + boff) * 4;
            cp16(bd, bsrc);
            cp16(bd + 16, bsrc + 4);
        }
        CP_COMMIT();
    };

    stage(0, 0);
    stage(1, 1);

    float acc[4][4][4];
#pragma unroll
    for (int a = 0; a < 4; a++)
#pragma unroll
        for (int b = 0; b < 4; b++)
#pragma unroll
            for (int c = 0; c < 4; c++) acc[a][b][c] = 0.f;

    for (int s = 0; s < NSTAGE; s++) {
        if (s < NSTAGE - 2) { CP_WAIT(1); } else { CP_WAIT(0); }
        __syncthreads();
        if (s + 2 < NSTAGE) stage(s + 2, (s + 2) % 3);

        const int buf = s % 3;
#pragma unroll
        for (int sub = 0; sub < 2; sub++) {
            half2* Asm = sbuf + buf * STAGE_H2 + sub * 2048;
            half2* Bsm = sbuf + buf * STAGE_H2 + 4096 + sub * 2048;
            uint4 AH[4], AL[4];
            uint2 BH[4], BL[4];
#pragma unroll
            for (int mt = 0; mt < 4; mt++) {
                half2* ab = Asm + (wm * 4 + mt) * 256;
                AH[mt] = *reinterpret_cast<uint4*>(ab + lane * 4);
                AL[mt] = *reinterpret_cast<uint4*>(ab + 128 + lane * 4);
            }
#pragma unroll
            for (int q = 0; q < 4; q++) {
                half2* bb = Bsm + (wn * 4 + q) * 128;
                BH[q] = *reinterpret_cast<uint2*>(bb + lane * 2);
                BL[q] = *reinterpret_cast<uint2*>(bb + 64 + lane * 2);
            }
#pragma unroll
            for (int q = 0; q < 4; q++)
#pragma unroll
                for (int mt = 0; mt < 4; mt++) {
                    mma_f16(acc[mt][q], AH[mt].x, AH[mt].y, AH[mt].z, AH[mt].w, BH[q].x, BH[q].y);
                    mma_f16(acc[mt][q], AH[mt].x, AH[mt].y, AH[mt].z, AH[mt].w, BL[q].x, BL[q].y);
                    mma_f16(acc[mt][q], AL[mt].x, AL[mt].y, AL[mt].z, AL[mt].w, BH[q].x, BH[q].y);
                }
        }

        if ((s & 7) == 7) {
            // end of K for this nch: fold c2, update argmin, reset acc
            const int nch = s >> 3;
#pragma unroll
            for (int q = 0; q < 4; q++) {
                int vbase = nch * 128 + (wn * 4 + q) * 8 + tig * 2;
                float c0 = c2s[vbase], c1 = c2s[vbase + 1];
#pragma unroll
                for (int mt = 0; mt < 4; mt++) {
                    float s0 = fmaf(-2.f, acc[mt][q][0], c0);
                    float s1 = fmaf(-2.f, acc[mt][q][1], c1);
                    float s2 = fmaf(-2.f, acc[mt][q][2], c0);
                    float s3 = fmaf(-2.f, acc[mt][q][3], c1);
                    int sl0 = mt * 2, sl1 = mt * 2 + 1;
                    if (s0 < bestv[sl0]) { bestv[sl0] = s0; besti[sl0] = vbase; }
                    if (s1 < bestv[sl0]) { bestv[sl0] = s1; besti[sl0] = vbase + 1; }
                    if (s2 < bestv[sl1]) { bestv[sl1] = s2; besti[sl1] = vbase; }
                    if (s3 < bestv[sl1]) { bestv[sl1] = s3; besti[sl1] = vbase + 1; }
                    acc[mt][q][0] = 0.f; acc[mt][q][1] = 0.f;
                    acc[mt][q][2] = 0.f; acc[mt][q][3] = 0.f;
                }
            }
        }
    }

    // cross-thread reduce: 16 candidates per row (aliases pipeline smem)
    __syncthreads();
#pragma unroll
    for (int mt = 0; mt < 4; mt++) {
#pragma unroll
        for (int h = 0; h < 2; h++) {
            int r = wm * 64 + mt * 16 + grp + h * 8;
            Sv[r * 16 + wn * 4 + tig] = bestv[mt * 2 + h];
            Si[r * 16 + wn * 4 + tig] = besti[mt * 2 + h];
        }
    }
    __syncthreads();
    if (tid < 128) {
        float bv = Sv[tid * 16];
        int   bi = Si[tid * 16];
#pragma unroll
        for (int u = 1; u < 16; u++) {
            float v2 = Sv[tid * 16 + u];
            int   i2 = Si[tid * 16 + u];
            if (v2 < bv || (v2 == bv && i2 < bi)) { bv = v2; bi = i2; }
        }
        ridx[tid] = bi;
        int b = btile * 128 + tid;
        out[(size_t)BB * TT * DD + (size_t)b * TT + t] = (float)bi;
    }
    __syncthreads();

    // gather epilogue
    const float4* cb4  = reinterpret_cast<const float4*>(cb);
    float4*       out4 = reinterpret_cast<float4*>(out);
    int rsub = tid >> 6, d4 = tid & 63;
#pragma unroll 4
    for (int r0 = 0; r0 < 128; r0 += 4) {
        int r   = r0 + rsub;
        int b   = btile * 128 + r;
        int idx = ridx[r];
        out4[((size_t)b * TT + t) * (DD / 4) + d4] =
            cb4[((size_t)t * VV + idx) * (DD / 4) + d4];
    }
}

// ---------------------------------------------------------------------------
#define DYN_SMEM (98304 + VV * 4)

extern "C" void kernel_launch(void* const* d_in, const int* in_sizes, int n_in,
                              void* d_out, int out_size) {
    const float* x  = (const float*)d_in[0];   // (B, T, D) f32
    const float* cb = (const float*)d_in[1];   // (T, V, D) f32
    float* out = (float*)d_out;

    cudaFuncSetAttribute(vsq_mma_kernel, cudaFuncAttributeMaxDynamicSharedMemorySize, DYN_SMEM);
    conv_x_kernel<<<dim3(128, TT), 128>>>(x);
    conv_c_kernel<<<dim3(64, TT), 128>>>(cb);
    vsq_mma_kernel<<<dim3(BB / 128, TT), 256, DYN_SMEM>>>(cb, out);
}

// round 8
// speedup vs baseline: 1.3326x; 1.0015x over previous
#include <cuda_runtime.h>
#include <cuda_fp16.h>
#include <cfloat>
#include <cstdint>

#define BB 2048
#define TT 32
#define VV 1024
#define DD 256

// ---------------- static device scratch -------------------------------------
__device__ float g_c2[TT * VV];                                  // 128 KB
// A fragments: [t][mtile16(128)][kstep(16)] blocks of 256 half2 (hi 128 | lo 128)
__device__ half2 g_xs[(size_t)TT * 128 * 16 * 256];              // 67 MB
// B fragments: [t][ntile8(128)][kstep(16)] blocks of 128 half2 (hi 64 | lo 64)
__device__ half2 g_cs[(size_t)TT * 128 * 16 * 128];              // 33.5 MB

// ---------------- helpers ----------------------------------------------------
__device__ __forceinline__ void mma_f16(float* c, uint32_t a0, uint32_t a1,
                                        uint32_t a2, uint32_t a3,
                                        uint32_t b0, uint32_t b1) {
    asm volatile(
        "mma.sync.aligned.m16n8k16.row.col.f32.f16.f16.f32 "
        "{%0,%1,%2,%3}, {%4,%5,%6,%7}, {%8,%9}, {%0,%1,%2,%3};"
        : "+f"(c[0]), "+f"(c[1]), "+f"(c[2]), "+f"(c[3])
        : "r"(a0), "r"(a1), "r"(a2), "r"(a3), "r"(b0), "r"(b1));
}
__device__ __forceinline__ uint32_t smem_u32(const void* p) {
    uint32_t a;
    asm("{ .reg .u64 t; cvta.to.shared.u64 t, %1; cvt.u32.u64 %0, t; }" : "=r"(a) : "l"(p));
    return a;
}
__device__ __forceinline__ void cp16(uint32_t dst, const void* src) {
    asm volatile("cp.async.cg.shared.global [%0], [%1], 16;" :: "r"(dst), "l"(src));
}
#define CP_COMMIT() asm volatile("cp.async.commit_group;")
#define CP_WAIT(n)  asm volatile("cp.async.wait_group %0;" :: "n"(n))

// ---------------- kernel 1: split X into A-fragment layout -------------------
__global__ __launch_bounds__(128) void conv_x_kernel(const float* __restrict__ x) {
    __shared__ float xs[16][258];
    const int mt = blockIdx.x, t = blockIdx.y, tid = threadIdx.x;
#pragma unroll
    for (int j = 0; j < 8; j++) {
        int f = tid + j * 128;
        int r = f >> 6, d4 = f & 63;
        float4 v = *reinterpret_cast<const float4*>(
            x + ((size_t)(mt * 16 + r) * TT + t) * DD + d4 * 4);
        xs[r][d4 * 4 + 0] = v.x; xs[r][d4 * 4 + 1] = v.y;
        xs[r][d4 * 4 + 2] = v.z; xs[r][d4 * 4 + 3] = v.w;
    }
    __syncthreads();
    const int lane = tid >> 2, r = tid & 3;
    const int tig = lane & 3;
    const int grp = lane >> 2;
    const int row = grp + (r & 1) * 8;
    half2* obase = g_xs + ((size_t)(t * 128 + mt) * 16) * 256;
#pragma unroll
    for (int ks = 0; ks < 16; ks++) {
        int k = ks * 16 + (r >> 1) * 8 + tig * 2;
        float v0 = xs[row][k], v1 = xs[row][k + 1];
        half h0 = __float2half_rn(v0), h1 = __float2half_rn(v1);
        half l0 = __float2half_rn(v0 - __half2float(h0));
        half l1 = __float2half_rn(v1 - __half2float(h1));
        obase[ks * 256 + tid]       = __halves2half2(h0, h1);
        obase[ks * 256 + 128 + tid] = __halves2half2(l0, l1);
    }
}

// ---------------- kernel 2: split C into B-fragment layout + c2 --------------
__global__ __launch_bounds__(128) void conv_c_kernel(const float* __restrict__ cb) {
    __shared__ float cs[16][258];
    __shared__ float psum[16][8];
    const int vt = blockIdx.x, t = blockIdx.y, tid = threadIdx.x;
#pragma unroll
    for (int j = 0; j < 8; j++) {
        int f = tid + j * 128;
        int r = f >> 6, d4 = f & 63;
        float4 v = *reinterpret_cast<const float4*>(
            cb + ((size_t)t * VV + vt * 16 + r) * DD + d4 * 4);
        cs[r][d4 * 4 + 0] = v.x; cs[r][d4 * 4 + 1] = v.y;
        cs[r][d4 * 4 + 2] = v.z; cs[r][d4 * 4 + 3] = v.w;
    }
    __syncthreads();
    {
        int r = tid >> 3, seg = tid & 7;
        float s = 0.f;
#pragma unroll
        for (int k = 0; k < 32; k++) {
            float v = cs[r][seg * 32 + k];
            s = fmaf(v, v, s);
        }
        psum[r][seg] = s;
    }
    const int s = tid >> 6, w = tid & 63;
    const int lane = w >> 1, rr = w & 1;
    const int grp = lane >> 2, tig = lane & 3;
    const int row = s * 8 + grp;
#pragma unroll
    for (int ks = 0; ks < 16; ks++) {
        int k = ks * 16 + rr * 8 + tig * 2;
        float v0 = cs[row][k], v1 = cs[row][k + 1];
        half h0 = __float2half_rn(v0), h1 = __float2half_rn(v1);
        half l0 = __float2half_rn(v0 - __half2float(h0));
        half l1 = __float2half_rn(v1 - __half2float(h1));
        half2* ob = g_cs + ((size_t)(t * 128 + vt * 2 + s) * 16 + ks) * 128;
        ob[w]      = __halves2half2(h0, h1);
        ob[64 + w] = __halves2half2(l0, l1);
    }
    __syncthreads();
    if (tid < 16) {
        float acc = 0.f;
#pragma unroll
        for (int j = 0; j < 8; j++) acc += psum[tid][j];
        g_c2[t * VV + vt * 16 + tid] = acc;
    }
}

// ---------------- main kernel ------------------------------------------------
// Grid (16, 32), 256 threads = 8 warps (2m x 4n). Warp tile 64x32, block 128x128.
// Stages of 2 k-steps (32KB), triple-buffered cp.async, ONE barrier per stage.
// MMA nest is TERM-OUTER: 16 independent accumulators between touches of the
// same accumulator -> no HMMA RAW chains.
#define STAGE_H2 8192                       // 32 KB per stage (A 16KB + B 16KB)
#define NSTAGE 64                           // 8 nch x 8 kspair

__global__ __launch_bounds__(256, 2)
void vsq_mma_kernel(const float* __restrict__ cb, float* __restrict__ out) {
    extern __shared__ char dyn[];
    half2* sbuf = reinterpret_cast<half2*>(dyn);            // 3 x 32KB
    float* c2s  = reinterpret_cast<float*>(dyn + 98304);    // 4KB
    float* Sv   = reinterpret_cast<float*>(dyn);            // [128][16] (alias)
    int*   Si   = reinterpret_cast<int*>(dyn + 8192);       // [128][16] (alias)
    int*   ridx = reinterpret_cast<int*>(dyn + 16384);      // [128]    (alias)

    const int tid = threadIdx.x;
    const int btile = blockIdx.x, t = blockIdx.y;
    const int wid = tid >> 5, lane = tid & 31;
    const int grp = lane >> 2, tig = lane & 3;
    const int wm = wid >> 2, wn = wid & 3;

    for (int i = tid; i < VV; i += 256) c2s[i] = g_c2[t * VV + i];
    __syncthreads();

    float bestv[8];
    int   besti[8];
#pragma unroll
    for (int i = 0; i < 8; i++) { bestv[i] = FLT_MAX; besti[i] = 0; }

    const half2* Abase = g_xs + ((size_t)(t * 128 + btile * 8) * 16) * 256;
    const half2* Bbase = g_cs + ((size_t)(t * 128)) * 16 * 128;

    const uint32_t sb0 = smem_u32(sbuf);
    const int nt8 = wid * 2 + (lane >> 4);
    const int boff = (lane & 15) * 8;
    auto stage = [&](int st, int buf) {
        const int nch = st >> 3, ks0 = (st & 7) * 2;
        uint32_t d = sb0 + (uint32_t)buf * STAGE_H2 * 4;
#pragma unroll
        for (int sub = 0; sub < 2; sub++) {
            int ks = ks0 + sub;
            const half2* asrc = Abase + ((size_t)(wid * 16 + ks)) * 256 + lane * 8;
            uint32_t ad = d + (sub * 2048 + wid * 256 + lane * 8) * 4;
            cp16(ad, asrc);
            cp16(ad + 16, asrc + 4);
            const half2* bsrc = Bbase + ((size_t)((nch * 16 + nt8) * 16 + ks)) * 128 + boff;
            uint32_t bd = d + (4096 + sub * 2048 + nt8 * 128 + boff) * 4;
            cp16(bd, bsrc);
            cp16(bd + 16, bsrc + 4);
        }
        CP_COMMIT();
    };

    stage(0, 0);
    stage(1, 1);

    float acc[4][4][4];
#pragma unroll
    for (int a = 0; a < 4; a++)
#pragma unroll
        for (int b = 0; b < 4; b++)
#pragma unroll
            for (int c = 0; c < 4; c++) acc[a][b][c] = 0.f;

    for (int s = 0; s < NSTAGE; s++) {
        if (s < NSTAGE - 2) { CP_WAIT(1); } else { CP_WAIT(0); }
        __syncthreads();
        if (s + 2 < NSTAGE) stage(s + 2, (s + 2) % 3);

        const int buf = s % 3;
#pragma unroll
        for (int sub = 0; sub < 2; sub++) {
            half2* Asm = sbuf + buf * STAGE_H2 + sub * 2048;
            half2* Bsm = sbuf + buf * STAGE_H2 + 4096 + sub * 2048;
            uint4 AH[4], AL[4];
            uint2 BH[4], BL[4];
#pragma unroll
            for (int mt = 0; mt < 4; mt++) {
                half2* ab = Asm + (wm * 4 + mt) * 256;
                AH[mt] = *reinterpret_cast<uint4*>(ab + lane * 4);
                AL[mt] = *reinterpret_cast<uint4*>(ab + 128 + lane * 4);
            }
#pragma unroll
            for (int q = 0; q < 4; q++) {
                half2* bb = Bsm + (wn * 4 + q) * 128;
                BH[q] = *reinterpret_cast<uint2*>(bb + lane * 2);
                BL[q] = *reinterpret_cast<uint2*>(bb + 64 + lane * 2);
            }
            // term-outer: 16 independent MMAs between touches of same acc
#pragma unroll
            for (int term = 0; term < 3; term++) {
#pragma unroll
                for (int q = 0; q < 4; q++)
#pragma unroll
                    for (int mt = 0; mt < 4; mt++) {
                        if (term == 0)
                            mma_f16(acc[mt][q], AH[mt].x, AH[mt].y, AH[mt].z, AH[mt].w,
                                    BH[q].x, BH[q].y);
                        else if (term == 1)
                            mma_f16(acc[mt][q], AH[mt].x, AH[mt].y, AH[mt].z, AH[mt].w,
                                    BL[q].x, BL[q].y);
                        else
                            mma_f16(acc[mt][q], AL[mt].x, AL[mt].y, AL[mt].z, AL[mt].w,
                                    BH[q].x, BH[q].y);
                    }
            }
        }

        if ((s & 7) == 7) {
            const int nch = s >> 3;
#pragma unroll
            for (int q = 0; q < 4; q++) {
                int vbase = nch * 128 + (wn * 4 + q) * 8 + tig * 2;
                float c0 = c2s[vbase], c1 = c2s[vbase + 1];
#pragma unroll
                for (int mt = 0; mt < 4; mt++) {
                    float s0 = fmaf(-2.f, acc[mt][q][0], c0);
                    float s1 = fmaf(-2.f, acc[mt][q][1], c1);
                    float s2 = fmaf(-2.f, acc[mt][q][2], c0);
                    float s3 = fmaf(-2.f, acc[mt][q][3], c1);
                    int sl0 = mt * 2, sl1 = mt * 2 + 1;
                    if (s0 < bestv[sl0]) { bestv[sl0] = s0; besti[sl0] = vbase; }
                    if (s1 < bestv[sl0]) { bestv[sl0] = s1; besti[sl0] = vbase + 1; }
                    if (s2 < bestv[sl1]) { bestv[sl1] = s2; besti[sl1] = vbase; }
                    if (s3 < bestv[sl1]) { bestv[sl1] = s3; besti[sl1] = vbase + 1; }
                    acc[mt][q][0] = 0.f; acc[mt][q][1] = 0.f;
                    acc[mt][q][2] = 0.f; acc[mt][q][3] = 0.f;
                }
            }
        }
    }

    // cross-thread reduce: 16 candidates per row (aliases pipeline smem)
    __syncthreads();
#pragma unroll
    for (int mt = 0; mt < 4; mt++) {
#pragma unroll
        for (int h = 0; h < 2; h++) {
            int r = wm * 64 + mt * 16 + grp + h * 8;
            Sv[r * 16 + wn * 4 + tig] = bestv[mt * 2 + h];
            Si[r * 16 + wn * 4 + tig] = besti[mt * 2 + h];
        }
    }
    __syncthreads();
    if (tid < 128) {
        float bv = Sv[tid * 16];
        int   bi = Si[tid * 16];
#pragma unroll
        for (int u = 1; u < 16; u++) {
            float v2 = Sv[tid * 16 + u];
            int   i2 = Si[tid * 16 + u];
            if (v2 < bv || (v2 == bv && i2 < bi)) { bv = v2; bi = i2; }
        }
        ridx[tid] = bi;
        int b = btile * 128 + tid;
        out[(size_t)BB * TT * DD + (size_t)b * TT + t] = (float)bi;
    }
    __syncthreads();

    // gather epilogue
    const float4* cb4  = reinterpret_cast<const float4*>(cb);
    float4*       out4 = reinterpret_cast<float4*>(out);
    int rsub = tid >> 6, d4 = tid & 63;
#pragma unroll 4
    for (int r0 = 0; r0 < 128; r0 += 4) {
        int r   = r0 + rsub;
        int b   = btile * 128 + r;
        int idx = ridx[r];
        out4[((size_t)b * TT + t) * (DD / 4) + d4] =
            cb4[((size_t)t * VV + idx) * (DD / 4) + d4];
    }
}

// ---------------------------------------------------------------------------
#define DYN_SMEM (98304 + VV * 4)

extern "C" void kernel_launch(void* const* d_in, const int* in_sizes, int n_in,
                              void* d_out, int out_size) {
    const float* x  = (const float*)d_in[0];   // (B, T, D) f32
    const float* cb = (const float*)d_in[1];   // (T, V, D) f32
    float* out = (float*)d_out;

    cudaFuncSetAttribute(vsq_mma_kernel, cudaFuncAttributeMaxDynamicSharedMemorySize, DYN_SMEM);
    conv_x_kernel<<<dim3(128, TT), 128>>>(x);
    conv_c_kernel<<<dim3(64, TT), 128>>>(cb);
    vsq_mma_kernel<<<dim3(BB / 128, TT), 256, DYN_SMEM>>>(cb, out);
}